// round 5
// baseline (speedup 1.0000x reference)
#include <cuda_runtime.h>
#include <cstdint>

#define NNODES 10000
#define NEDGES 320000

// Scratch (no cudaMalloc allowed)
static __device__ float g_Ai[NNODES * 8];    // node features after MLP
static __device__ float g_T[NNODES * 72];    // T[n][c][u], c in 0..8, u in 0..7
static __device__ float g_cnt[NNODES];       // in-degree (float)

// ---------------------------------------------------------------- helpers
__device__ __forceinline__ float silu(float t) {
    return __fdividef(t, 1.0f + __expf(-t));
}

__device__ __forceinline__ void red4(float* p, float x, float y, float z, float w) {
    asm volatile("red.global.add.v4.f32 [%0], {%1,%2,%3,%4};"
                 :: "l"(p), "f"(x), "f"(y), "f"(z), "f"(w) : "memory");
}
__device__ __forceinline__ void red1(float* p, float x) {
    asm volatile("red.global.add.f32 [%0], %1;" :: "l"(p), "f"(x) : "memory");
}
__device__ __forceinline__ unsigned long long pack2(float a, float b) {
    unsigned long long r;
    asm("mov.b64 %0, {%1, %2};" : "=l"(r) : "f"(a), "f"(b));
    return r;
}
__device__ __forceinline__ void unpack2(unsigned long long v, float& a, float& b) {
    asm("mov.b64 {%0, %1}, %2;" : "=f"(a), "=f"(b) : "l"(v));
}
__device__ __forceinline__ unsigned long long fma2(unsigned long long a,
                                                   unsigned long long b,
                                                   unsigned long long c) {
    unsigned long long d;
    asm("fma.rn.f32x2 %0, %1, %2, %3;" : "=l"(d) : "l"(a), "l"(b), "l"(c));
    return d;
}

// ---------------------------------------------------------------- zero scratch
__global__ void zero_kernel() {
    int i = blockIdx.x * blockDim.x + threadIdx.x;
    if (i < NNODES * 72) g_T[i] = 0.0f;
    if (i < NNODES) g_cnt[i] = 0.0f;
}

// ---------------------------------------------------------------- node MLP
// Ai = silu(atom_emb[A] @ mlp_w1 + mlp_b1) @ mlp_w2 + mlp_b2    (N, 8)
__global__ void node_mlp_kernel(const float* __restrict__ atom_emb,
                                const float* __restrict__ w1,   // (16,64)
                                const float* __restrict__ b1,   // (64,)
                                const float* __restrict__ w2,   // (64,8)
                                const float* __restrict__ b2,   // (8,)
                                const int* __restrict__ A, int N)
{
    int n = blockIdx.x * blockDim.x + threadIdx.x;
    if (n >= N) return;
    const float* emb = atom_emb + 16 * __ldg(A + n);
    float e[16];
#pragma unroll
    for (int i = 0; i < 16; i++) e[i] = __ldg(emb + i);
    float acc[8];
#pragma unroll
    for (int v = 0; v < 8; v++) acc[v] = 0.0f;
#pragma unroll 4
    for (int j = 0; j < 64; j++) {
        float t = __ldg(b1 + j);
#pragma unroll
        for (int i = 0; i < 16; i++) t = fmaf(e[i], __ldg(w1 + i * 64 + j), t);
        float h = silu(t);
#pragma unroll
        for (int v = 0; v < 8; v++) acc[v] = fmaf(h, __ldg(w2 + j * 8 + v), acc[v]);
    }
#pragma unroll
    for (int v = 0; v < 8; v++) g_Ai[8 * n + v] = acc[v] + __ldg(b2 + v);
}

// ---------------------------------------------------------------- edge kernel
// Per edge: geometry -> harmonics -> radial MLP gates -> scatter T[dst].
__global__ __launch_bounds__(128) void edge_kernel(
    const float* __restrict__ pos,
    const float* __restrict__ shifts,
    const float* __restrict__ cell,
    const float* __restrict__ fw1, const float* __restrict__ fb1,  // (10,64),(64,)
    const float* __restrict__ fw2, const float* __restrict__ fb2,  // (64,64),(64,)
    const float* __restrict__ fw3, const float* __restrict__ fb3,  // (64,15),(15,)
    const int* __restrict__ batch,
    const int* __restrict__ esrc, const int* __restrict__ edst, int E)
{
    int e = blockIdx.x * blockDim.x + threadIdx.x;
    if (e >= E) return;
    int s = __ldg(esrc + e);
    int d = __ldg(edst + e);

    // shift = edge_shifts[e] @ cell[batch[src]]
    float s0 = __ldg(shifts + 3 * e + 0);
    float s1 = __ldg(shifts + 3 * e + 1);
    float s2 = __ldg(shifts + 3 * e + 2);
    const float* C = cell + 9 * __ldg(batch + s);
    float shx = s0 * __ldg(C + 0) + s1 * __ldg(C + 3) + s2 * __ldg(C + 6);
    float shy = s0 * __ldg(C + 1) + s1 * __ldg(C + 4) + s2 * __ldg(C + 7);
    float shz = s0 * __ldg(C + 2) + s1 * __ldg(C + 5) + s2 * __ldg(C + 8);

    float vx = __ldg(pos + 3 * d + 0) - __ldg(pos + 3 * s + 0) + shx;
    float vy = __ldg(pos + 3 * d + 1) - __ldg(pos + 3 * s + 1) + shy;
    float vz = __ldg(pos + 3 * d + 2) - __ldg(pos + 3 * s + 2) + shz;
    float r = sqrtf(vx * vx + vy * vy + vz * vz);
    float inv = __fdividef(1.0f, fmaxf(r, 1e-8f));
    float nx = vx * inv, ny = vy * inv, nz = vz * inv;

    // radial basis: d_i = r/step - (i+1), step = 5/11
    float rb[10];
    {
        float rr = r * 2.2f;  // 11/5
#pragma unroll
        for (int i = 0; i < 10; i++) {
            float dd = rr - (float)(i + 1);
            rb[i] = __expf(-dd * dd) * 2.8234622f;  // sqrt(10)/1.12
        }
    }

    // g2pre = silu(rb@fw1+fb1) @ fw2 accumulated with packed f32x2
    unsigned long long acc2[32];
#pragma unroll
    for (int q = 0; q < 32; q++) acc2[q] = 0ULL;
#pragma unroll 4
    for (int i = 0; i < 64; i++) {
        float t = __ldg(fb1 + i);
#pragma unroll
        for (int k = 0; k < 10; k++) t = fmaf(rb[k], __ldg(fw1 + k * 64 + i), t);
        float h = silu(t);
        unsigned long long hh = pack2(h, h);
        const ulonglong2* row = (const ulonglong2*)(fw2 + i * 64);
#pragma unroll
        for (int q = 0; q < 16; q++) {
            ulonglong2 wp = __ldg(row + q);
            acc2[2 * q + 0] = fma2(hh, wp.x, acc2[2 * q + 0]);
            acc2[2 * q + 1] = fma2(hh, wp.y, acc2[2 * q + 1]);
        }
    }

    // gates for paths p=0 (l=0), p=3 (l=1), p=9 (l=2)
    float g0 = __ldg(fb3 + 0);
    float gA = __ldg(fb3 + 3);
    float gB = __ldg(fb3 + 9);
#pragma unroll
    for (int q = 0; q < 32; q++) {
        float t0, t1;
        unpack2(acc2[q], t0, t1);
        int j = 2 * q;
        float h0 = silu(t0 + __ldg(fb2 + j));
        float h1 = silu(t1 + __ldg(fb2 + j + 1));
        g0 = fmaf(h0, __ldg(fw3 + j * 15 + 0), fmaf(h1, __ldg(fw3 + (j + 1) * 15 + 0), g0));
        gA = fmaf(h0, __ldg(fw3 + j * 15 + 3), fmaf(h1, __ldg(fw3 + (j + 1) * 15 + 3), gA));
        gB = fmaf(h0, __ldg(fw3 + j * 15 + 9), fmaf(h1, __ldg(fw3 + (j + 1) * 15 + 9), gB));
    }

    // 9 coefficients: gate_l * Y_l[k]
    float coef[9];
    coef[0] = g0;
    float gAs = gA * 1.7320508f;  // sqrt(3)
    coef[1] = gAs * nx;
    coef[2] = gAs * ny;
    coef[3] = gAs * nz;
    float a15 = gB * 3.8729833f;   // sqrt(15)
    coef[4] = a15 * nx * ny;
    coef[5] = a15 * ny * nz;
    coef[6] = gB * 1.1180340f * (3.0f * nz * nz - 1.0f);  // sqrt(5)/2
    coef[7] = a15 * nx * nz;
    coef[8] = gB * 1.9364917f * (nx * nx - ny * ny);      // sqrt(15)/2

    // source node features
    const float4* ap = (const float4*)(g_Ai + 8 * s);
    float4 a0 = ap[0];
    float4 a1 = ap[1];

    float* Tn = g_T + 72 * d;
#pragma unroll
    for (int c = 0; c < 9; c++) {
        float cc = coef[c];
        red4(Tn + 8 * c + 0, cc * a0.x, cc * a0.y, cc * a0.z, cc * a0.w);
        red4(Tn + 8 * c + 4, cc * a1.x, cc * a1.y, cc * a1.z, cc * a1.w);
    }
    red1(g_cnt + d, 1.0f);
}

// ---------------------------------------------------------------- node epilogue
// One warp per node, lane = output channel w (0..31).
// out[n, off_l + w*dim_l + k] = (1/cnt) * sum_u (sum_v Ai[n,v] W_l[u,v,w]) * T[n,c_l+k,u]
__global__ void node_out_kernel(const float* __restrict__ tpw,  // (15,8,8,32)
                                float* __restrict__ out, int N)
{
    int gt = blockIdx.x * blockDim.x + threadIdx.x;
    int n = gt >> 5;
    int w = gt & 31;
    if (n >= N) return;

    float av[8];
#pragma unroll
    for (int v = 0; v < 8; v++) av[v] = __ldg(g_Ai + 8 * n + v);
    float invc = __fdividef(1.0f, fmaxf(g_cnt[n], 1.0f));
    const float* Tn = g_T + 72 * n;
    float* on = out + 288 * n;

    const int PIDX[3] = {0, 3, 9};
    const int CB[3]   = {0, 1, 4};
    const int DIM[3]  = {1, 3, 5};
    const int OFF[3]  = {0, 32, 128};

#pragma unroll
    for (int l = 0; l < 3; l++) {
        const float* W = tpw + PIDX[l] * 2048;
        float wv[8];
#pragma unroll
        for (int u = 0; u < 8; u++) {
            float sacc = 0.0f;
#pragma unroll
            for (int v = 0; v < 8; v++)
                sacc = fmaf(av[v], __ldg(W + u * 256 + v * 32 + w), sacc);
            wv[u] = sacc;
        }
#pragma unroll
        for (int k = 0; k < DIM[l]; k++) {
            float sacc = 0.0f;
#pragma unroll
            for (int u = 0; u < 8; u++)
                sacc = fmaf(wv[u], __ldg(Tn + (CB[l] + k) * 8 + u), sacc);
            on[OFF[l] + w * DIM[l] + k] = invc * sacc;
        }
    }
}

// ---------------------------------------------------------------- launch
extern "C" void kernel_launch(void* const* d_in, const int* in_sizes, int n_in,
                              void* d_out, int out_size)
{
    const float* pos      = (const float*)d_in[0];
    const float* shifts   = (const float*)d_in[1];
    const float* cell     = (const float*)d_in[2];
    const float* atom_emb = (const float*)d_in[3];
    const float* mw1      = (const float*)d_in[4];
    const float* mb1      = (const float*)d_in[5];
    const float* mw2      = (const float*)d_in[6];
    const float* mb2      = (const float*)d_in[7];
    const float* fw1      = (const float*)d_in[8];
    const float* fb1      = (const float*)d_in[9];
    const float* fw2      = (const float*)d_in[10];
    const float* fb2      = (const float*)d_in[11];
    const float* fw3      = (const float*)d_in[12];
    const float* fb3      = (const float*)d_in[13];
    const float* tpw      = (const float*)d_in[14];
    const int*   A        = (const int*)d_in[15];
    const int*   batch    = (const int*)d_in[16];
    const int*   esrc     = (const int*)d_in[17];
    const int*   edst     = (const int*)d_in[18];

    int N = in_sizes[15]; if (N > NNODES) N = NNODES;
    int E = in_sizes[17]; if (E > NEDGES) E = NEDGES;

    zero_kernel<<<(NNODES * 72 + 255) / 256, 256>>>();
    node_mlp_kernel<<<(N + 127) / 128, 128>>>(atom_emb, mw1, mb1, mw2, mb2, A, N);
    edge_kernel<<<(E + 127) / 128, 128>>>(pos, shifts, cell,
                                          fw1, fb1, fw2, fb2, fw3, fb3,
                                          batch, esrc, edst, E);
    node_out_kernel<<<(N * 32 + 255) / 256, 256>>>(tpw, (float*)d_out, N);
}

// round 6
// speedup vs baseline: 1.6426x; 1.6426x over previous
#include <cuda_runtime.h>
#include <cstdint>

#define NNODES 10000
#define NEDGES 320000
#define LUTN 8192
#define LUT_RMAX 8.0f

// Scratch (no cudaMalloc allowed)
static __device__ float  g_Ai[NNODES * 8];    // node features after MLP
static __device__ float  g_T[NNODES * 72];    // T[n][c][u], c in 0..8, u in 0..7
static __device__ float  g_cnt[NNODES];       // in-degree (float)
static __device__ float4 g_lut[LUTN];         // (g0, gA, gB, -) vs r

// ---------------------------------------------------------------- helpers
__device__ __forceinline__ float silu(float t) {
    return __fdividef(t, 1.0f + __expf(-t));
}

__device__ __forceinline__ void red4(float* p, float x, float y, float z, float w) {
    asm volatile("red.global.add.v4.f32 [%0], {%1,%2,%3,%4};"
                 :: "l"(p), "f"(x), "f"(y), "f"(z), "f"(w) : "memory");
}
__device__ __forceinline__ void red1(float* p, float x) {
    asm volatile("red.global.add.f32 [%0], %1;" :: "l"(p), "f"(x) : "memory");
}
__device__ __forceinline__ unsigned long long pack2(float a, float b) {
    unsigned long long r;
    asm("mov.b64 %0, {%1, %2};" : "=l"(r) : "f"(a), "f"(b));
    return r;
}
__device__ __forceinline__ void unpack2(unsigned long long v, float& a, float& b) {
    asm("mov.b64 {%0, %1}, %2;" : "=f"(a), "=f"(b) : "l"(v));
}
__device__ __forceinline__ unsigned long long fma2(unsigned long long a,
                                                   unsigned long long b,
                                                   unsigned long long c) {
    unsigned long long d;
    asm("fma.rn.f32x2 %0, %1, %2, %3;" : "=l"(d) : "l"(a), "l"(b), "l"(c));
    return d;
}

// ---------------------------------------------------------------- zero scratch
__global__ void zero_kernel() {
    int i = blockIdx.x * blockDim.x + threadIdx.x;
    if (i < NNODES * 72) g_T[i] = 0.0f;
    if (i < NNODES) g_cnt[i] = 0.0f;
}

// ---------------------------------------------------------------- gate LUT
// gates(r) is a scalar function of edge length only. Tabulate it once.
__global__ __launch_bounds__(128) void lut_kernel(
    const float* __restrict__ fw1, const float* __restrict__ fb1,  // (10,64),(64,)
    const float* __restrict__ fw2, const float* __restrict__ fb2,  // (64,64),(64,)
    const float* __restrict__ fw3, const float* __restrict__ fb3)  // (64,15),(15,)
{
    int j = blockIdx.x * blockDim.x + threadIdx.x;
    if (j >= LUTN) return;
    float r = (float)j * (LUT_RMAX / (float)(LUTN - 1));

    // radial basis: d_i = r/step - (i+1), step = 5/11
    float rb[10];
    float rr = r * 2.2f;
#pragma unroll
    for (int i = 0; i < 10; i++) {
        float dd = rr - (float)(i + 1);
        rb[i] = __expf(-dd * dd) * 2.8234622f;  // sqrt(10)/1.12
    }

    // silu(rb@fw1+fb1) @ fw2 accumulated with packed f32x2
    unsigned long long acc2[32];
#pragma unroll
    for (int q = 0; q < 32; q++) acc2[q] = 0ULL;
#pragma unroll 4
    for (int i = 0; i < 64; i++) {
        float t = __ldg(fb1 + i);
#pragma unroll
        for (int k = 0; k < 10; k++) t = fmaf(rb[k], __ldg(fw1 + k * 64 + i), t);
        float h = silu(t);
        unsigned long long hh = pack2(h, h);
        const ulonglong2* row = (const ulonglong2*)(fw2 + i * 64);
#pragma unroll
        for (int q = 0; q < 16; q++) {
            ulonglong2 wp = __ldg(row + q);
            acc2[2 * q + 0] = fma2(hh, wp.x, acc2[2 * q + 0]);
            acc2[2 * q + 1] = fma2(hh, wp.y, acc2[2 * q + 1]);
        }
    }

    float g0 = __ldg(fb3 + 0);
    float gA = __ldg(fb3 + 3);
    float gB = __ldg(fb3 + 9);
#pragma unroll
    for (int q = 0; q < 32; q++) {
        float t0, t1;
        unpack2(acc2[q], t0, t1);
        int jj = 2 * q;
        float h0 = silu(t0 + __ldg(fb2 + jj));
        float h1 = silu(t1 + __ldg(fb2 + jj + 1));
        g0 = fmaf(h0, __ldg(fw3 + jj * 15 + 0), fmaf(h1, __ldg(fw3 + (jj + 1) * 15 + 0), g0));
        gA = fmaf(h0, __ldg(fw3 + jj * 15 + 3), fmaf(h1, __ldg(fw3 + (jj + 1) * 15 + 3), gA));
        gB = fmaf(h0, __ldg(fw3 + jj * 15 + 9), fmaf(h1, __ldg(fw3 + (jj + 1) * 15 + 9), gB));
    }
    g_lut[j] = make_float4(g0, gA, gB, 0.0f);
}

// ---------------------------------------------------------------- node MLP
__global__ void node_mlp_kernel(const float* __restrict__ atom_emb,
                                const float* __restrict__ w1,   // (16,64)
                                const float* __restrict__ b1,   // (64,)
                                const float* __restrict__ w2,   // (64,8)
                                const float* __restrict__ b2,   // (8,)
                                const int* __restrict__ A, int N)
{
    int n = blockIdx.x * blockDim.x + threadIdx.x;
    if (n >= N) return;
    const float* emb = atom_emb + 16 * __ldg(A + n);
    float e[16];
#pragma unroll
    for (int i = 0; i < 16; i++) e[i] = __ldg(emb + i);
    float acc[8];
#pragma unroll
    for (int v = 0; v < 8; v++) acc[v] = 0.0f;
#pragma unroll 4
    for (int j = 0; j < 64; j++) {
        float t = __ldg(b1 + j);
#pragma unroll
        for (int i = 0; i < 16; i++) t = fmaf(e[i], __ldg(w1 + i * 64 + j), t);
        float h = silu(t);
#pragma unroll
        for (int v = 0; v < 8; v++) acc[v] = fmaf(h, __ldg(w2 + j * 8 + v), acc[v]);
    }
#pragma unroll
    for (int v = 0; v < 8; v++) g_Ai[8 * n + v] = acc[v] + __ldg(b2 + v);
}

// ---------------------------------------------------------------- edge kernel
// Per edge: geometry -> LUT gates -> harmonics -> scatter T[dst].
__global__ __launch_bounds__(256) void edge_kernel(
    const float* __restrict__ pos,
    const float* __restrict__ shifts,
    const float* __restrict__ cell,
    const int* __restrict__ batch,
    const int* __restrict__ esrc, const int* __restrict__ edst, int E)
{
    int e = blockIdx.x * blockDim.x + threadIdx.x;
    if (e >= E) return;
    int s = __ldg(esrc + e);
    int d = __ldg(edst + e);

    float s0 = __ldg(shifts + 3 * e + 0);
    float s1 = __ldg(shifts + 3 * e + 1);
    float s2 = __ldg(shifts + 3 * e + 2);
    float shx = 0.0f, shy = 0.0f, shz = 0.0f;
    if (s0 != 0.0f || s1 != 0.0f || s2 != 0.0f) {
        const float* C = cell + 9 * __ldg(batch + s);
        shx = s0 * __ldg(C + 0) + s1 * __ldg(C + 3) + s2 * __ldg(C + 6);
        shy = s0 * __ldg(C + 1) + s1 * __ldg(C + 4) + s2 * __ldg(C + 7);
        shz = s0 * __ldg(C + 2) + s1 * __ldg(C + 5) + s2 * __ldg(C + 8);
    }

    float vx = __ldg(pos + 3 * d + 0) - __ldg(pos + 3 * s + 0) + shx;
    float vy = __ldg(pos + 3 * d + 1) - __ldg(pos + 3 * s + 1) + shy;
    float vz = __ldg(pos + 3 * d + 2) - __ldg(pos + 3 * s + 2) + shz;
    float r = sqrtf(vx * vx + vy * vy + vz * vz);
    float inv = __fdividef(1.0f, fmaxf(r, 1e-8f));
    float nx = vx * inv, ny = vy * inv, nz = vz * inv;

    // gates via LUT (linear interpolation; clamped — gates are constant for r > ~6.5)
    float t = fminf(r * ((float)(LUTN - 1) / LUT_RMAX), (float)(LUTN - 1));
    int li = (int)t;
    li = li > LUTN - 2 ? LUTN - 2 : li;
    float fr = t - (float)li;
    float4 la = __ldg(&g_lut[li]);
    float4 lb = __ldg(&g_lut[li + 1]);
    float g0 = fmaf(fr, lb.x - la.x, la.x);
    float gA = fmaf(fr, lb.y - la.y, la.y);
    float gB = fmaf(fr, lb.z - la.z, la.z);

    // 9 coefficients: gate_l * Y_l[k]
    float coef[9];
    coef[0] = g0;
    float gAs = gA * 1.7320508f;  // sqrt(3)
    coef[1] = gAs * nx;
    coef[2] = gAs * ny;
    coef[3] = gAs * nz;
    float a15 = gB * 3.8729833f;   // sqrt(15)
    coef[4] = a15 * nx * ny;
    coef[5] = a15 * ny * nz;
    coef[6] = gB * 1.1180340f * (3.0f * nz * nz - 1.0f);  // sqrt(5)/2
    coef[7] = a15 * nx * nz;
    coef[8] = gB * 1.9364917f * (nx * nx - ny * ny);      // sqrt(15)/2

    const float4* ap = (const float4*)(g_Ai + 8 * s);
    float4 a0 = ap[0];
    float4 a1 = ap[1];

    float* Tn = g_T + 72 * d;
#pragma unroll
    for (int c = 0; c < 9; c++) {
        float cc = coef[c];
        red4(Tn + 8 * c + 0, cc * a0.x, cc * a0.y, cc * a0.z, cc * a0.w);
        red4(Tn + 8 * c + 4, cc * a1.x, cc * a1.y, cc * a1.z, cc * a1.w);
    }
    red1(g_cnt + d, 1.0f);
}

// ---------------------------------------------------------------- node epilogue
// 8 warps/block, one node per warp, lane = output channel w. tpw slices in smem.
__global__ __launch_bounds__(256) void node_out_kernel(
    const float* __restrict__ tpw,  // (15,8,8,32)
    float* __restrict__ out, int N)
{
    __shared__ float sW[3 * 2048];
    // Load the three used path slices (p = 0, 3, 9) into shared memory.
    {
        const float* src0 = tpw;            // p=0
        const float* src1 = tpw + 3 * 2048; // p=3
        const float* src2 = tpw + 9 * 2048; // p=9
        for (int i = threadIdx.x; i < 2048; i += 256) {
            sW[i]          = __ldg(src0 + i);
            sW[2048 + i]   = __ldg(src1 + i);
            sW[4096 + i]   = __ldg(src2 + i);
        }
    }
    __syncthreads();

    int warp = threadIdx.x >> 5;
    int w = threadIdx.x & 31;
    int n = blockIdx.x * 8 + warp;
    if (n >= N) return;

    float av[8];
#pragma unroll
    for (int v = 0; v < 8; v++) av[v] = __ldg(g_Ai + 8 * n + v);
    float invc = __fdividef(1.0f, fmaxf(g_cnt[n], 1.0f));
    const float* Tn = g_T + 72 * n;
    float* on = out + 288 * n;

    const int CB[3]  = {0, 1, 4};
    const int DIM[3] = {1, 3, 5};
    const int OFF[3] = {0, 32, 128};

#pragma unroll
    for (int l = 0; l < 3; l++) {
        const float* W = sW + l * 2048;
        float wv[8];
#pragma unroll
        for (int u = 0; u < 8; u++) {
            float sacc = 0.0f;
#pragma unroll
            for (int v = 0; v < 8; v++)
                sacc = fmaf(av[v], W[u * 256 + v * 32 + w], sacc);
            wv[u] = sacc;
        }
#pragma unroll
        for (int k = 0; k < DIM[l]; k++) {
            float sacc = 0.0f;
#pragma unroll
            for (int u = 0; u < 8; u++)
                sacc = fmaf(wv[u], __ldg(Tn + (CB[l] + k) * 8 + u), sacc);
            on[OFF[l] + w * DIM[l] + k] = invc * sacc;
        }
    }
}

// ---------------------------------------------------------------- launch
extern "C" void kernel_launch(void* const* d_in, const int* in_sizes, int n_in,
                              void* d_out, int out_size)
{
    const float* pos      = (const float*)d_in[0];
    const float* shifts   = (const float*)d_in[1];
    const float* cell     = (const float*)d_in[2];
    const float* atom_emb = (const float*)d_in[3];
    const float* mw1      = (const float*)d_in[4];
    const float* mb1      = (const float*)d_in[5];
    const float* mw2      = (const float*)d_in[6];
    const float* mb2      = (const float*)d_in[7];
    const float* fw1      = (const float*)d_in[8];
    const float* fb1      = (const float*)d_in[9];
    const float* fw2      = (const float*)d_in[10];
    const float* fb2      = (const float*)d_in[11];
    const float* fw3      = (const float*)d_in[12];
    const float* fb3      = (const float*)d_in[13];
    const float* tpw      = (const float*)d_in[14];
    const int*   A        = (const int*)d_in[15];
    const int*   batch    = (const int*)d_in[16];
    const int*   esrc     = (const int*)d_in[17];
    const int*   edst     = (const int*)d_in[18];

    int N = in_sizes[15]; if (N > NNODES) N = NNODES;
    int E = in_sizes[17]; if (E > NEDGES) E = NEDGES;

    zero_kernel<<<(NNODES * 72 + 255) / 256, 256>>>();
    lut_kernel<<<LUTN / 128, 128>>>(fw1, fb1, fw2, fb2, fw3, fb3);
    node_mlp_kernel<<<(N + 127) / 128, 128>>>(atom_emb, mw1, mb1, mw2, mb2, A, N);
    edge_kernel<<<(E + 255) / 256, 256>>>(pos, shifts, cell, batch, esrc, edst, E);
    node_out_kernel<<<(N + 7) / 8, 256>>>(tpw, (float*)d_out, N);
}

// round 8
// speedup vs baseline: 1.9626x; 1.1948x over previous
#include <cuda_runtime.h>
#include <cstdint>

#define NNODES 10000
#define NEDGES 320000
#define LUTN 8192
#define LUT_RMAX 8.0f

// Scratch (no cudaMalloc allowed)
static __device__ float  g_Ai[NNODES * 8];    // node features after MLP
static __device__ float  g_T[NNODES * 72];    // T[n][c][u], c in 0..8, u in 0..7
static __device__ float  g_cnt[NNODES + 24];  // in-degree (padded for float4 zeroing)
static __device__ float4 g_lut[LUTN];         // (g0, gA, gB, -) vs r

// Prologue grid partition
#define ZB   184   // zero blocks: 184*256 threads * 4 float4 each = 188416 >= 182506
#define LB   32    // lut blocks:  32*256 = 8192
#define MB   40    // mlp blocks:  40*256 = 10240 >= 10000

// ---------------------------------------------------------------- helpers
__device__ __forceinline__ float silu(float t) {
    return __fdividef(t, 1.0f + __expf(-t));
}
__device__ __forceinline__ void red4(float* p, float x, float y, float z, float w) {
    asm volatile("red.global.add.v4.f32 [%0], {%1,%2,%3,%4};"
                 :: "l"(p), "f"(x), "f"(y), "f"(z), "f"(w) : "memory");
}
__device__ __forceinline__ void red1(float* p, float x) {
    asm volatile("red.global.add.f32 [%0], %1;" :: "l"(p), "f"(x) : "memory");
}
__device__ __forceinline__ unsigned long long pack2(float a, float b) {
    unsigned long long r;
    asm("mov.b64 %0, {%1, %2};" : "=l"(r) : "f"(a), "f"(b));
    return r;
}
__device__ __forceinline__ void unpack2(unsigned long long v, float& a, float& b) {
    asm("mov.b64 {%0, %1}, %2;" : "=f"(a), "=f"(b) : "l"(v));
}
__device__ __forceinline__ unsigned long long fma2(unsigned long long a,
                                                   unsigned long long b,
                                                   unsigned long long c) {
    unsigned long long d;
    asm("fma.rn.f32x2 %0, %1, %2, %3;" : "=l"(d) : "l"(a), "l"(b), "l"(c));
    return d;
}

// ---------------------------------------------------------------- fused prologue
// blocks [0,ZB): zero g_T + g_cnt (grid-stride float4 stores, FULL coverage)
// blocks [ZB,ZB+LB): build gate LUT (gates are a scalar function of r only)
// blocks [ZB+LB,ZB+LB+MB): node MLP -> g_Ai
__global__ __launch_bounds__(256) void prologue_kernel(
    const float* __restrict__ fw1, const float* __restrict__ fb1,  // (10,64),(64,)
    const float* __restrict__ fw2, const float* __restrict__ fb2,  // (64,64),(64,)
    const float* __restrict__ fw3, const float* __restrict__ fb3,  // (64,15),(15,)
    const float* __restrict__ atom_emb,
    const float* __restrict__ w1,   // (16,64)
    const float* __restrict__ b1,   // (64,)
    const float* __restrict__ w2,   // (64,8)
    const float* __restrict__ b2,   // (8,)
    const int* __restrict__ A, int N)
{
    int blk = blockIdx.x;

    if (blk < ZB) {
        // ---- zero scratch (grid-stride: 182506 float4 slots over 47104 threads) ----
        const int NT4  = (NNODES * 72) / 4;              // 180000
        const int NC4  = (NNODES + 24) / 4;              // 2506
        const int TOT4 = NT4 + NC4;                      // 182506
        const float4 z = make_float4(0.f, 0.f, 0.f, 0.f);
        for (int idx = blk * 256 + threadIdx.x; idx < TOT4; idx += ZB * 256) {
            if (idx < NT4) ((float4*)g_T)[idx] = z;
            else           ((float4*)g_cnt)[idx - NT4] = z;
        }
        return;
    }

    if (blk < ZB + LB) {
        // ---- gate LUT ----
        int j = (blk - ZB) * 256 + threadIdx.x;
        float r = (float)j * (LUT_RMAX / (float)(LUTN - 1));

        float rb[10];
        float rr = r * 2.2f;   // 11/5
#pragma unroll
        for (int i = 0; i < 10; i++) {
            float dd = rr - (float)(i + 1);
            rb[i] = __expf(-dd * dd) * 2.8234622f;  // sqrt(10)/1.12
        }

        unsigned long long acc2[32];
#pragma unroll
        for (int q = 0; q < 32; q++) acc2[q] = 0ULL;
#pragma unroll 4
        for (int i = 0; i < 64; i++) {
            float t = __ldg(fb1 + i);
#pragma unroll
            for (int k = 0; k < 10; k++) t = fmaf(rb[k], __ldg(fw1 + k * 64 + i), t);
            float h = silu(t);
            unsigned long long hh = pack2(h, h);
            const ulonglong2* row = (const ulonglong2*)(fw2 + i * 64);
#pragma unroll
            for (int q = 0; q < 16; q++) {
                ulonglong2 wp = __ldg(row + q);
                acc2[2 * q + 0] = fma2(hh, wp.x, acc2[2 * q + 0]);
                acc2[2 * q + 1] = fma2(hh, wp.y, acc2[2 * q + 1]);
            }
        }

        float g0 = __ldg(fb3 + 0);
        float gA = __ldg(fb3 + 3);
        float gB = __ldg(fb3 + 9);
#pragma unroll
        for (int q = 0; q < 32; q++) {
            float t0, t1;
            unpack2(acc2[q], t0, t1);
            int jj = 2 * q;
            float h0 = silu(t0 + __ldg(fb2 + jj));
            float h1 = silu(t1 + __ldg(fb2 + jj + 1));
            g0 = fmaf(h0, __ldg(fw3 + jj * 15 + 0), fmaf(h1, __ldg(fw3 + (jj + 1) * 15 + 0), g0));
            gA = fmaf(h0, __ldg(fw3 + jj * 15 + 3), fmaf(h1, __ldg(fw3 + (jj + 1) * 15 + 3), gA));
            gB = fmaf(h0, __ldg(fw3 + jj * 15 + 9), fmaf(h1, __ldg(fw3 + (jj + 1) * 15 + 9), gB));
        }
        g_lut[j] = make_float4(g0, gA, gB, 0.0f);
        return;
    }

    // ---- node MLP ----
    {
        int n = (blk - ZB - LB) * 256 + threadIdx.x;
        if (n >= N) return;
        const float* emb = atom_emb + 16 * __ldg(A + n);
        float e[16];
#pragma unroll
        for (int i = 0; i < 16; i++) e[i] = __ldg(emb + i);
        float acc[8];
#pragma unroll
        for (int v = 0; v < 8; v++) acc[v] = 0.0f;
#pragma unroll 4
        for (int j = 0; j < 64; j++) {
            float t = __ldg(b1 + j);
#pragma unroll
            for (int i = 0; i < 16; i++) t = fmaf(e[i], __ldg(w1 + i * 64 + j), t);
            float h = silu(t);
#pragma unroll
            for (int v = 0; v < 8; v++) acc[v] = fmaf(h, __ldg(w2 + j * 8 + v), acc[v]);
        }
#pragma unroll
        for (int v = 0; v < 8; v++) g_Ai[8 * n + v] = acc[v] + __ldg(b2 + v);
    }
}

// ---------------------------------------------------------------- edge kernel
// Per edge: geometry -> LUT gates -> harmonics -> scatter T[dst].
__global__ __launch_bounds__(256) void edge_kernel(
    const float* __restrict__ pos,
    const float* __restrict__ shifts,
    const float* __restrict__ cell,
    const int* __restrict__ batch,
    const int* __restrict__ esrc, const int* __restrict__ edst, int E)
{
    int e = blockIdx.x * blockDim.x + threadIdx.x;
    if (e >= E) return;
    int s = __ldg(esrc + e);
    int d = __ldg(edst + e);

    float s0 = __ldg(shifts + 3 * e + 0);
    float s1 = __ldg(shifts + 3 * e + 1);
    float s2 = __ldg(shifts + 3 * e + 2);
    float shx = 0.0f, shy = 0.0f, shz = 0.0f;
    if (s0 != 0.0f || s1 != 0.0f || s2 != 0.0f) {
        const float* C = cell + 9 * __ldg(batch + s);
        shx = s0 * __ldg(C + 0) + s1 * __ldg(C + 3) + s2 * __ldg(C + 6);
        shy = s0 * __ldg(C + 1) + s1 * __ldg(C + 4) + s2 * __ldg(C + 7);
        shz = s0 * __ldg(C + 2) + s1 * __ldg(C + 5) + s2 * __ldg(C + 8);
    }

    float vx = __ldg(pos + 3 * d + 0) - __ldg(pos + 3 * s + 0) + shx;
    float vy = __ldg(pos + 3 * d + 1) - __ldg(pos + 3 * s + 1) + shy;
    float vz = __ldg(pos + 3 * d + 2) - __ldg(pos + 3 * s + 2) + shz;
    float r = sqrtf(vx * vx + vy * vy + vz * vz);
    float inv = __fdividef(1.0f, fmaxf(r, 1e-8f));
    float nx = vx * inv, ny = vy * inv, nz = vz * inv;

    // gates via LUT (linear interpolation; gates constant for r > ~6.5)
    float t = fminf(r * ((float)(LUTN - 1) / LUT_RMAX), (float)(LUTN - 1));
    int li = (int)t;
    li = li > LUTN - 2 ? LUTN - 2 : li;
    float fr = t - (float)li;
    float4 la = __ldg(&g_lut[li]);
    float4 lb = __ldg(&g_lut[li + 1]);
    float g0 = fmaf(fr, lb.x - la.x, la.x);
    float gA = fmaf(fr, lb.y - la.y, la.y);
    float gB = fmaf(fr, lb.z - la.z, la.z);

    // 9 coefficients: gate_l * Y_l[k]
    float coef[9];
    coef[0] = g0;
    float gAs = gA * 1.7320508f;  // sqrt(3)
    coef[1] = gAs * nx;
    coef[2] = gAs * ny;
    coef[3] = gAs * nz;
    float a15 = gB * 3.8729833f;   // sqrt(15)
    coef[4] = a15 * nx * ny;
    coef[5] = a15 * ny * nz;
    coef[6] = gB * 1.1180340f * (3.0f * nz * nz - 1.0f);  // sqrt(5)/2
    coef[7] = a15 * nx * nz;
    coef[8] = gB * 1.9364917f * (nx * nx - ny * ny);      // sqrt(15)/2

    const float4* ap = (const float4*)(g_Ai + 8 * s);
    float4 a0 = ap[0];
    float4 a1 = ap[1];

    float* Tn = g_T + 72 * d;
#pragma unroll
    for (int c = 0; c < 9; c++) {
        float cc = coef[c];
        red4(Tn + 8 * c + 0, cc * a0.x, cc * a0.y, cc * a0.z, cc * a0.w);
        red4(Tn + 8 * c + 4, cc * a1.x, cc * a1.y, cc * a1.z, cc * a1.w);
    }
    red1(g_cnt + d, 1.0f);
}

// ---------------------------------------------------------------- node epilogue
// 8 warps/block, one node per warp, lane = output channel w. tpw slices in smem.
__global__ __launch_bounds__(256) void node_out_kernel(
    const float* __restrict__ tpw,  // (15,8,8,32)
    float* __restrict__ out, int N)
{
    __shared__ float sW[3 * 2048];
    {
        const float* src0 = tpw;            // p=0
        const float* src1 = tpw + 3 * 2048; // p=3
        const float* src2 = tpw + 9 * 2048; // p=9
        for (int i = threadIdx.x; i < 2048; i += 256) {
            sW[i]        = __ldg(src0 + i);
            sW[2048 + i] = __ldg(src1 + i);
            sW[4096 + i] = __ldg(src2 + i);
        }
    }
    __syncthreads();

    int warp = threadIdx.x >> 5;
    int w = threadIdx.x & 31;
    int n = blockIdx.x * 8 + warp;
    if (n >= N) return;

    float av[8];
#pragma unroll
    for (int v = 0; v < 8; v++) av[v] = __ldg(g_Ai + 8 * n + v);
    float invc = __fdividef(1.0f, fmaxf(g_cnt[n], 1.0f));
    const float* Tn = g_T + 72 * n;
    float* on = out + 288 * n;

    const int CB[3]  = {0, 1, 4};
    const int DIM[3] = {1, 3, 5};
    const int OFF[3] = {0, 32, 128};

#pragma unroll
    for (int l = 0; l < 3; l++) {
        const float* W = sW + l * 2048;
        float wv[8];
#pragma unroll
        for (int u = 0; u < 8; u++) {
            float sacc = 0.0f;
#pragma unroll
            for (int v = 0; v < 8; v++)
                sacc = fmaf(av[v], W[u * 256 + v * 32 + w], sacc);
            wv[u] = sacc;
        }
#pragma unroll
        for (int k = 0; k < DIM[l]; k++) {
            float sacc = 0.0f;
#pragma unroll
            for (int u = 0; u < 8; u++)
                sacc = fmaf(wv[u], __ldg(Tn + (CB[l] + k) * 8 + u), sacc);
            on[OFF[l] + w * DIM[l] + k] = invc * sacc;
        }
    }
}

// ---------------------------------------------------------------- launch
extern "C" void kernel_launch(void* const* d_in, const int* in_sizes, int n_in,
                              void* d_out, int out_size)
{
    const float* pos      = (const float*)d_in[0];
    const float* shifts   = (const float*)d_in[1];
    const float* cell     = (const float*)d_in[2];
    const float* atom_emb = (const float*)d_in[3];
    const float* mw1      = (const float*)d_in[4];
    const float* mb1      = (const float*)d_in[5];
    const float* mw2      = (const float*)d_in[6];
    const float* mb2      = (const float*)d_in[7];
    const float* fw1      = (const float*)d_in[8];
    const float* fb1      = (const float*)d_in[9];
    const float* fw2      = (const float*)d_in[10];
    const float* fb2      = (const float*)d_in[11];
    const float* fw3      = (const float*)d_in[12];
    const float* fb3      = (const float*)d_in[13];
    const float* tpw      = (const float*)d_in[14];
    const int*   A        = (const int*)d_in[15];
    const int*   batch    = (const int*)d_in[16];
    const int*   esrc     = (const int*)d_in[17];
    const int*   edst     = (const int*)d_in[18];

    int N = in_sizes[15]; if (N > NNODES) N = NNODES;
    int E = in_sizes[17]; if (E > NEDGES) E = NEDGES;

    prologue_kernel<<<ZB + LB + MB, 256>>>(fw1, fb1, fw2, fb2, fw3, fb3,
                                           atom_emb, mw1, mb1, mw2, mb2, A, N);
    edge_kernel<<<(E + 255) / 256, 256>>>(pos, shifts, cell, batch, esrc, edst, E);
    node_out_kernel<<<(N + 7) / 8, 256>>>(tpw, (float*)d_out, N);
}